// round 15
// baseline (speedup 1.0000x reference)
#include <cuda_runtime.h>
#include <cuda_fp16.h>
#include <cstdint>
#include <math.h>

#define B_ 16
#define D_ 37
#define F_ 4096
#define I_ 64

// ---- scratch (static device globals: allocation-free) ----
__device__ __half g_qh[B_ * F_ * I_];                // [b][f][i], LN'd, *0.125*log2e, fp16
__device__ __half g_kh[B_ * F_ * I_];                // [b][f][i], LN'd, fp16
__device__ float  g_v [B_ * F_ * I_];                // [b][f][i], LN'd fp32
__device__ __half g_vs[B_ * F_ * I_];                // Vs[b][n][i] = v[n][i]/c[n], fp16

#define SW128B(o) ((o) ^ (((o) >> 3) & 0x70))

// ======================= PTX helpers (arch-generic, sm_80+) ==================
__device__ __forceinline__ unsigned smem_u32(const void* p) {
    unsigned a;
    asm("{ .reg .u64 t; cvta.to.shared.u64 t, %1; cvt.u32.u64 %0, t; }"
        : "=r"(a) : "l"(p));
    return a;
}
__device__ __forceinline__ void cp_async16(unsigned dst, const void* src) {
    asm volatile("cp.async.cg.shared.global [%0], [%1], 16;" :: "r"(dst), "l"(src));
}
__device__ __forceinline__ void cp_commit() {
    asm volatile("cp.async.commit_group;" ::: "memory");
}
template <int N>
__device__ __forceinline__ void cp_wait() {
    asm volatile("cp.async.wait_group %0;" :: "n"(N) : "memory");
}
__device__ __forceinline__ void ldm_x4(unsigned* r, unsigned addr) {
    asm volatile("ldmatrix.sync.aligned.m8n8.x4.shared.b16 {%0,%1,%2,%3}, [%4];"
                 : "=r"(r[0]), "=r"(r[1]), "=r"(r[2]), "=r"(r[3]) : "r"(addr));
}
__device__ __forceinline__ void ldm_x4_t(unsigned* r, unsigned addr) {
    asm volatile("ldmatrix.sync.aligned.m8n8.x4.trans.shared.b16 {%0,%1,%2,%3}, [%4];"
                 : "=r"(r[0]), "=r"(r[1]), "=r"(r[2]), "=r"(r[3]) : "r"(addr));
}
__device__ __forceinline__ void mma_f16(float* c, const unsigned* a,
                                        unsigned b0, unsigned b1) {
    asm volatile(
        "mma.sync.aligned.m16n8k16.row.col.f32.f16.f16.f32 "
        "{%0,%1,%2,%3}, {%4,%5,%6,%7}, {%8,%9}, {%0,%1,%2,%3};"
        : "+f"(c[0]), "+f"(c[1]), "+f"(c[2]), "+f"(c[3])
        : "r"(a[0]), "r"(a[1]), "r"(a[2]), "r"(a[3]), "r"(b0), "r"(b1));
}
// pack (lo, hi) -> half2 and take 2^x elementwise in fp16
__device__ __forceinline__ unsigned ex2_h2(float hi, float lo) {
    unsigned p, o;
    asm("cvt.rn.f16x2.f32 %0, %1, %2;" : "=r"(p) : "f"(hi), "f"(lo));
    asm("ex2.approx.f16x2 %0, %1;" : "=r"(o) : "r"(p));
    return o;
}

// ---------------------------------------------------------------------------
// Kernel 1: q/k/v = LN(x^T @ W). Block = 64 consecutive f.
// Weights repacked in smem as interleaved float2 (cols l, l+32) and x read
// as LDS.128 pairs -> 20 smem ops per 4-d chunk instead of 56.
// q scaled by 0.125*log2(e) so downstream uses raw ex2.
// ---------------------------------------------------------------------------
__device__ __forceinline__ void ln64(float& a0, float& a1, float scale) {
    float s = a0 + a1;
    #pragma unroll
    for (int o = 16; o; o >>= 1) s += __shfl_xor_sync(0xffffffffu, s, o);
    float mu = s * (1.0f / 64.0f);
    float t0 = a0 - mu, t1 = a1 - mu;
    float ss = t0 * t0 + t1 * t1;
    #pragma unroll
    for (int o = 16; o; o >>= 1) ss += __shfl_xor_sync(0xffffffffu, ss, o);
    float r = rsqrtf(ss * (1.0f / 64.0f) + 1e-5f) * scale;
    a0 = t0 * r; a1 = t1 * r;
}

__global__ void __launch_bounds__(256) qkv_ln_kernel(
    const float* __restrict__ x,
    const float* __restrict__ Wq,
    const float* __restrict__ Wk,
    const float* __restrict__ Wv)
{
    __shared__ float sW2[3 * D_ * 64];  // interleaved: [(g*D+d)*32 + l]*2 + h
    __shared__ float sx[D_ * 64];       // 9472 B
    int tid = threadIdx.x;
    int b  = blockIdx.x >> 6;
    int f0 = (blockIdx.x & 63) << 6;

    for (int idx = tid; idx < 3 * D_ * 64; idx += 256) {
        int g = idx / (D_ * 64), rem = idx % (D_ * 64);
        int d = rem >> 6, i = rem & 63;
        const float* W = (g == 0) ? Wq : (g == 1) ? Wk : Wv;
        sW2[(((g * D_ + d) * 32 + (i & 31)) << 1) + (i >> 5)] = W[d * I_ + i];
    }
    for (int i = tid; i < D_ * 64; i += 256) {
        int d = i >> 6, c = i & 63;
        sx[i] = x[(size_t)b * D_ * F_ + (size_t)d * F_ + f0 + c];
    }
    __syncthreads();

    int warp = tid >> 5, lane = tid & 31;
    int fbase = warp * 8;

    float acc[8][6] = {};
    #pragma unroll
    for (int dc = 0; dc < 40; dc += 4) {
        float wr[4][6];
        float xj[4][8];
        #pragma unroll
        for (int dd = 0; dd < 4; ++dd) {
            int d = dc + dd;
            if (d < D_) {
                float2 wq = *(float2*)&sW2[((0 * D_ + d) * 32 + lane) << 1];
                float2 wk = *(float2*)&sW2[((1 * D_ + d) * 32 + lane) << 1];
                float2 wv = *(float2*)&sW2[((2 * D_ + d) * 32 + lane) << 1];
                wr[dd][0] = wq.x; wr[dd][1] = wq.y;
                wr[dd][2] = wk.x; wr[dd][3] = wk.y;
                wr[dd][4] = wv.x; wr[dd][5] = wv.y;
                *(float4*)&xj[dd][0] = *(float4*)&sx[d * 64 + fbase];
                *(float4*)&xj[dd][4] = *(float4*)&sx[d * 64 + fbase + 4];
            } else {
                #pragma unroll
                for (int u = 0; u < 6; ++u) wr[dd][u] = 0.0f;
                #pragma unroll
                for (int u = 0; u < 8; ++u) xj[dd][u] = 0.0f;
            }
        }
        #pragma unroll
        for (int j = 0; j < 8; ++j) {
            #pragma unroll
            for (int dd = 0; dd < 4; ++dd) {
                float xd = xj[dd][j];
                acc[j][0] += xd * wr[dd][0];
                acc[j][1] += xd * wr[dd][1];
                acc[j][2] += xd * wr[dd][2];
                acc[j][3] += xd * wr[dd][3];
                acc[j][4] += xd * wr[dd][4];
                acc[j][5] += xd * wr[dd][5];
            }
        }
    }

    #pragma unroll
    for (int j = 0; j < 8; ++j) {
        ln64(acc[j][0], acc[j][1], 0.18033688f);   // 0.125 * log2(e)
        ln64(acc[j][2], acc[j][3], 1.0f);
        ln64(acc[j][4], acc[j][5], 1.0f);
        size_t ov = ((size_t)b * F_ + f0 + fbase + j) * I_ + lane;
        g_qh[ov] = __float2half_rn(acc[j][0]); g_qh[ov + 32] = __float2half_rn(acc[j][1]);
        g_kh[ov] = __float2half_rn(acc[j][2]); g_kh[ov + 32] = __float2half_rn(acc[j][3]);
        g_v [ov] = acc[j][4];                  g_v [ov + 32] = acc[j][5];
    }
}

// ---------------------------------------------------------------------------
// Kernel 2 (pass 1): c[n] = sum_m 2^(S[m][n]) AND g_vs = v/c, fused.
// S'[n][m] = k[n]·q[m] via fp16 mma. CTA owns n-tile 128 (warp: 32 n rows);
// m looped in 64-chunks (3-stage q ring, ONE sync per chunk). Row sums live
// in regs; c staged in 512B smem; epilogue scales v -> vs for the same rows.
// ---------------------------------------------------------------------------
#define C1_SK   0u
#define C1_SQ   16384u
#define C1_QST  8192u
#define C1_SC   40960
#define C1_SMEM (40960 + 512)

__global__ void __launch_bounds__(128) colsum_kernel() {
    extern __shared__ char sm[];
    unsigned sb = smem_u32(sm);
    float* scol = (float*)(sm + C1_SC);

    int tid = threadIdx.x, lane = tid & 31, w = tid >> 5;
    int n0 = blockIdx.x * 128, b = blockIdx.y;

    const __half* kv = g_kh + ((size_t)b * F_ + n0) * I_;
    const __half* qv = g_qh + (size_t)b * F_ * I_;

    int r = tid >> 3, c16 = tid & 7;
    // group 0: resident k tile + q chunk 0
    #pragma unroll
    for (int j = 0; j < 8; ++j) {
        int row = r + j * 16;
        cp_async16(sb + C1_SK + SW128B((unsigned)(row * 128 + c16 * 16)),
                   kv + (size_t)row * I_ + c16 * 8);
    }
    #pragma unroll
    for (int j = 0; j < 4; ++j) {
        int row = r + j * 16;
        cp_async16(sb + C1_SQ + SW128B((unsigned)(row * 128 + c16 * 16)),
                   qv + (size_t)row * I_ + c16 * 8);
    }
    cp_commit();
    // group 1: q chunk 1
    #pragma unroll
    for (int j = 0; j < 4; ++j) {
        int row = r + j * 16;
        cp_async16(sb + C1_SQ + C1_QST + SW128B((unsigned)(row * 128 + c16 * 16)),
                   qv + (size_t)(64 + row) * I_ + c16 * 8);
    }
    cp_commit();

    unsigned a_lrow = (unsigned)((lane & 7) + ((lane >> 3) & 1) * 8);
    unsigned a_koff = (unsigned)((lane >> 4) << 4);
    unsigned b_lrow = (unsigned)((lane & 7) + ((lane >> 4) << 3));
    unsigned b_koff = (unsigned)(((lane >> 3) & 1) << 4);

    float sumA[2] = {}, sumB[2] = {};   // rows r0 / r0+8 per mf

    int bs = 0;                          // t % 3
    for (int t = 0; t < F_ / 64; ++t) {
        cp_wait<1>();
        __syncthreads();                 // buf t ready; compute(t-1) done everywhere

        // prefetch q chunk t+2 into buffer (t+2)%3 == (t-1)%3 (safe after sync)
        if (t + 2 < F_ / 64) {
            int nb = bs - 1; if (nb < 0) nb += 3;
            unsigned qd = sb + C1_SQ + (unsigned)nb * C1_QST;
            int kc = (t + 2) * 64;
            #pragma unroll
            for (int j = 0; j < 4; ++j) {
                int row = r + j * 16;
                cp_async16(qd + SW128B((unsigned)(row * 128 + c16 * 16)),
                           qv + (size_t)(kc + row) * I_ + c16 * 8);
            }
            cp_commit();
        }

        unsigned qbuf = sb + C1_SQ + (unsigned)bs * C1_QST;

        float acc[2][8][4] = {};
        #pragma unroll
        for (int ks = 0; ks < 4; ++ks) {
            unsigned a[2][4], bB[4][4];
            #pragma unroll
            for (int mf = 0; mf < 2; ++mf) {
                unsigned row = (unsigned)(w * 32 + mf * 16) + a_lrow;
                ldm_x4(a[mf], sb + C1_SK + SW128B(row * 128 + a_koff + ks * 32));
            }
            #pragma unroll
            for (int np = 0; np < 4; ++np) {
                unsigned row = (unsigned)(np * 16) + b_lrow;
                ldm_x4(bB[np], qbuf + SW128B(row * 128 + b_koff + ks * 32));
            }
            #pragma unroll
            for (int mf = 0; mf < 2; ++mf)
                #pragma unroll
                for (int nf = 0; nf < 8; ++nf) {
                    int np = nf >> 1, s = nf & 1;
                    mma_f16(acc[mf][nf], a[mf], bB[np][2 * s], bB[np][2 * s + 1]);
                }
        }

        #pragma unroll
        for (int mf = 0; mf < 2; ++mf)
            #pragma unroll
            for (int nf = 0; nf < 8; ++nf) {
                unsigned p01 = ex2_h2(acc[mf][nf][1], acc[mf][nf][0]);  // row r0
                unsigned p23 = ex2_h2(acc[mf][nf][3], acc[mf][nf][2]);  // row r0+8
                __half2 h01 = *(__half2*)&p01;
                __half2 h23 = *(__half2*)&p23;
                sumA[mf] += __low2float(h01) + __high2float(h01);
                sumB[mf] += __low2float(h23) + __high2float(h23);
            }

        if (++bs == 3) bs = 0;
    }

    // reduce across the 4 lanes sharing a row (different c2)
    #pragma unroll
    for (int o = 1; o <= 2; o <<= 1)
        #pragma unroll
        for (int mf = 0; mf < 2; ++mf) {
            sumA[mf] += __shfl_xor_sync(0xffffffffu, sumA[mf], o);
            sumB[mf] += __shfl_xor_sync(0xffffffffu, sumB[mf], o);
        }
    if ((lane & 3) == 0) {
        int nl = w * 32 + (lane >> 2);
        #pragma unroll
        for (int mf = 0; mf < 2; ++mf) {
            scol[nl + mf * 16]     = sumA[mf];
            scol[nl + mf * 16 + 8] = sumB[mf];
        }
    }
    __syncthreads();

    // ---- fused vscale: g_vs[row][i] = fp16(v[row][i] / c[row]) ----
    {
        int row = tid >> 1;
        int ih = (tid & 1) * 32;
        float rc = 1.0f / scol[row];
        const float* vp = g_v + ((size_t)b * F_ + n0 + row) * I_ + ih;
        __half* vo = g_vs + ((size_t)b * F_ + n0 + row) * I_ + ih;
        #pragma unroll
        for (int u = 0; u < 4; ++u) {
            float4 v0 = *(const float4*)(vp + u * 8);
            float4 v1 = *(const float4*)(vp + u * 8 + 4);
            __half2 h[4];
            h[0] = __floats2half2_rn(v0.x * rc, v0.y * rc);
            h[1] = __floats2half2_rn(v0.z * rc, v0.w * rc);
            h[2] = __floats2half2_rn(v1.x * rc, v1.y * rc);
            h[3] = __floats2half2_rn(v1.z * rc, v1.w * rc);
            *(uint4*)(vo + u * 8) = *(uint4*)h;
        }
        int row2 = row + 64;
        float rc2 = 1.0f / scol[row2];
        const float* vp2 = g_v + ((size_t)b * F_ + n0 + row2) * I_ + ih;
        __half* vo2 = g_vs + ((size_t)b * F_ + n0 + row2) * I_ + ih;
        #pragma unroll
        for (int u = 0; u < 4; ++u) {
            float4 v0 = *(const float4*)(vp2 + u * 8);
            float4 v1 = *(const float4*)(vp2 + u * 8 + 4);
            __half2 h[4];
            h[0] = __floats2half2_rn(v0.x * rc2, v0.y * rc2);
            h[1] = __floats2half2_rn(v0.z * rc2, v0.w * rc2);
            h[2] = __floats2half2_rn(v1.x * rc2, v1.y * rc2);
            h[3] = __floats2half2_rn(v1.z * rc2, v1.w * rc2);
            *(uint4*)(vo2 + u * 8) = *(uint4*)h;
        }
    }
}

// ---------------------------------------------------------------------------
// Kernel 3 (pass 2): fused QK -> 2^S -> AV. No P in global memory.
// CTA: 128 thr, m-tile 128 (warp: 32 m rows), q tile resident in smem.
// n looped in 64-chunks with a 3-stage k/v ring and ONE sync per chunk.
// The ex2.f16x2 C->A conversion is interleaved PER k16-STEP with the AV mma
// so MUFU work hides under the HMMA issue stream.
// ---------------------------------------------------------------------------
#define F2_SQ   0u
#define F2_ST   16384u      // 3 stages x (k 8KB + v 8KB)
#define F2_STSZ 16384u
#define F2_SMEM (16384 + 3 * 16384)

__global__ void __launch_bounds__(128, 3) fused_av_kernel(float* __restrict__ out) {
    extern __shared__ char sm[];
    unsigned sb = smem_u32(sm);

    int tid = threadIdx.x, lane = tid & 31, w = tid >> 5;
    int m0 = blockIdx.x * 128, b = blockIdx.y;

    const __half* qv = g_qh + ((size_t)b * F_ + m0) * I_;
    const __half* kv = g_kh + (size_t)b * F_ * I_;
    const __half* vv = g_vs + (size_t)b * F_ * I_;

    int r = tid >> 3, c16 = tid & 7;
    // group 0: q tile + k0 + v0
    #pragma unroll
    for (int j = 0; j < 8; ++j) {
        int row = r + j * 16;
        cp_async16(sb + F2_SQ + SW128B((unsigned)(row * 128 + c16 * 16)),
                   qv + (size_t)row * I_ + c16 * 8);
    }
    #pragma unroll
    for (int j = 0; j < 4; ++j) {
        int row = r + j * 16;
        cp_async16(sb + F2_ST + SW128B((unsigned)(row * 128 + c16 * 16)),
                   kv + (size_t)row * I_ + c16 * 8);
        cp_async16(sb + F2_ST + 8192u + SW128B((unsigned)(row * 128 + c16 * 16)),
                   vv + (size_t)row * I_ + c16 * 8);
    }
    cp_commit();
    // group 1: k1 + v1
    #pragma unroll
    for (int j = 0; j < 4; ++j) {
        int row = r + j * 16;
        cp_async16(sb + F2_ST + F2_STSZ + SW128B((unsigned)(row * 128 + c16 * 16)),
                   kv + (size_t)(64 + row) * I_ + c16 * 8);
        cp_async16(sb + F2_ST + F2_STSZ + 8192u + SW128B((unsigned)(row * 128 + c16 * 16)),
                   vv + (size_t)(64 + row) * I_ + c16 * 8);
    }
    cp_commit();

    unsigned a_lrow = (unsigned)((lane & 7) + ((lane >> 3) & 1) * 8);
    unsigned a_koff = (unsigned)((lane >> 4) << 4);
    unsigned b_lrow = (unsigned)((lane & 7) + ((lane >> 4) << 3));
    unsigned b_koff = (unsigned)(((lane >> 3) & 1) << 4);
    unsigned bt_base = (unsigned)((lane & 15) * 128 + ((lane >> 4) << 4));

    float acc_o[2][8][4] = {};     // persistent output accumulator

    int bs = 0;                    // t % 3
    for (int t = 0; t < F_ / 64; ++t) {
        cp_wait<1>();
        __syncthreads();           // buf t ready; compute(t-1) done everywhere

        // prefetch chunk t+2 into buffer (t+2)%3 == (t-1)%3 (safe after sync)
        if (t + 2 < F_ / 64) {
            int nb = bs - 1; if (nb < 0) nb += 3;
            unsigned kd = sb + F2_ST + (unsigned)nb * F2_STSZ;
            int kc = (t + 2) * 64;
            #pragma unroll
            for (int j = 0; j < 4; ++j) {
                int row = r + j * 16;
                cp_async16(kd + SW128B((unsigned)(row * 128 + c16 * 16)),
                           kv + (size_t)(kc + row) * I_ + c16 * 8);
                cp_async16(kd + 8192u + SW128B((unsigned)(row * 128 + c16 * 16)),
                           vv + (size_t)(kc + row) * I_ + c16 * 8);
            }
            cp_commit();
        }

        unsigned kbuf = sb + F2_ST + (unsigned)bs * F2_STSZ;
        unsigned vbuf = kbuf + 8192u;

        // ---- S mma: S[m 32][n 64] fragments ----
        float acc_s[2][8][4] = {};
        #pragma unroll
        for (int ks = 0; ks < 4; ++ks) {
            unsigned a[2][4], bB[4][4];
            #pragma unroll
            for (int mf = 0; mf < 2; ++mf) {
                unsigned row = (unsigned)(w * 32 + mf * 16) + a_lrow;
                ldm_x4(a[mf], sb + F2_SQ + SW128B(row * 128 + a_koff + ks * 32));
            }
            #pragma unroll
            for (int np = 0; np < 4; ++np) {
                unsigned row = (unsigned)(np * 16) + b_lrow;
                ldm_x4(bB[np], kbuf + SW128B(row * 128 + b_koff + ks * 32));
            }
            #pragma unroll
            for (int mf = 0; mf < 2; ++mf)
                #pragma unroll
                for (int nf = 0; nf < 8; ++nf) {
                    int np = nf >> 1, s = nf & 1;
                    mma_f16(acc_s[mf][nf], a[mf], bB[np][2 * s], bB[np][2 * s + 1]);
                }
        }

        // ---- per-k16-step: ex2 conversion (FA2 register identity) + AV mma ----
        #pragma unroll
        for (int s = 0; s < 4; ++s) {
            unsigned pa[2][4];
            #pragma unroll
            for (int mf = 0; mf < 2; ++mf) {
                pa[mf][0] = ex2_h2(acc_s[mf][2 * s][1],     acc_s[mf][2 * s][0]);
                pa[mf][1] = ex2_h2(acc_s[mf][2 * s][3],     acc_s[mf][2 * s][2]);
                pa[mf][2] = ex2_h2(acc_s[mf][2 * s + 1][1], acc_s[mf][2 * s + 1][0]);
                pa[mf][3] = ex2_h2(acc_s[mf][2 * s + 1][3], acc_s[mf][2 * s + 1][2]);
            }
            unsigned bv[4][4];
            #pragma unroll
            for (int p = 0; p < 4; ++p)
                ldm_x4_t(bv[p], vbuf + SW128B(bt_base + s * 2048 + p * 32));
            #pragma unroll
            for (int mf = 0; mf < 2; ++mf)
                #pragma unroll
                for (int p = 0; p < 4; ++p) {
                    mma_f16(acc_o[mf][2 * p],     pa[mf], bv[p][0], bv[p][1]);
                    mma_f16(acc_o[mf][2 * p + 1], pa[mf], bv[p][2], bv[p][3]);
                }
        }

        if (++bs == 3) bs = 0;
    }

    int r0 = lane >> 2, c2 = (lane & 3) * 2;
    #pragma unroll
    for (int mf = 0; mf < 2; ++mf) {
        int mrow = m0 + w * 32 + mf * 16 + r0;
        float* o0 = out + ((size_t)b * F_ + mrow) * I_ + c2;
        float* o1 = o0 + 8 * I_;
        #pragma unroll
        for (int it = 0; it < 8; ++it) {
            *(float2*)(o0 + it * 8) = make_float2(acc_o[mf][it][0], acc_o[mf][it][1]);
            *(float2*)(o1 + it * 8) = make_float2(acc_o[mf][it][2], acc_o[mf][it][3]);
        }
    }
}

// ---------------------------------------------------------------------------
extern "C" void kernel_launch(void* const* d_in, const int* in_sizes, int n_in,
                              void* d_out, int out_size)
{
    const float* x  = (const float*)d_in[0];
    const float* Wq = (const float*)d_in[1];
    const float* Wk = (const float*)d_in[2];
    const float* Wv = (const float*)d_in[3];
    float* out = (float*)d_out;

    static bool attr_done = false;
    if (!attr_done) {
        cudaFuncSetAttribute(colsum_kernel,
                             cudaFuncAttributeMaxDynamicSharedMemorySize, C1_SMEM);
        cudaFuncSetAttribute(fused_av_kernel,
                             cudaFuncAttributeMaxDynamicSharedMemorySize, F2_SMEM);
        attr_done = true;
    }

    qkv_ln_kernel<<<B_ * F_ / 64, 256>>>(x, Wq, Wk, Wv);
    colsum_kernel<<<dim3(F_ / 128, B_), 128, C1_SMEM>>>();
    fused_av_kernel<<<dim3(F_ / 128, B_), 128, F2_SMEM>>>(out);
}

// round 16
// speedup vs baseline: 1.0176x; 1.0176x over previous
#include <cuda_runtime.h>
#include <cuda_fp16.h>
#include <cstdint>
#include <math.h>

#define B_ 16
#define D_ 37
#define F_ 4096
#define I_ 64

// ---- scratch (static device globals: allocation-free) ----
__device__ __half g_qh[B_ * F_ * I_];                // [b][f][i], LN'd, *0.125*log2e, fp16
__device__ __half g_kh[B_ * F_ * I_];                // [b][f][i], LN'd, fp16
__device__ float  g_v [B_ * F_ * I_];                // [b][f][i], LN'd fp32
__device__ __half g_vs[B_ * F_ * I_];                // Vs[b][n][i] = v[n][i]/c[n], fp16

#define SW128B(o) ((o) ^ (((o) >> 3) & 0x70))

// ======================= PTX helpers (arch-generic, sm_80+) ==================
__device__ __forceinline__ unsigned smem_u32(const void* p) {
    unsigned a;
    asm("{ .reg .u64 t; cvta.to.shared.u64 t, %1; cvt.u32.u64 %0, t; }"
        : "=r"(a) : "l"(p));
    return a;
}
__device__ __forceinline__ void cp_async16(unsigned dst, const void* src) {
    asm volatile("cp.async.cg.shared.global [%0], [%1], 16;" :: "r"(dst), "l"(src));
}
__device__ __forceinline__ void cp_commit() {
    asm volatile("cp.async.commit_group;" ::: "memory");
}
template <int N>
__device__ __forceinline__ void cp_wait() {
    asm volatile("cp.async.wait_group %0;" :: "n"(N) : "memory");
}
__device__ __forceinline__ void ldm_x4(unsigned* r, unsigned addr) {
    asm volatile("ldmatrix.sync.aligned.m8n8.x4.shared.b16 {%0,%1,%2,%3}, [%4];"
                 : "=r"(r[0]), "=r"(r[1]), "=r"(r[2]), "=r"(r[3]) : "r"(addr));
}
__device__ __forceinline__ void ldm_x4_t(unsigned* r, unsigned addr) {
    asm volatile("ldmatrix.sync.aligned.m8n8.x4.trans.shared.b16 {%0,%1,%2,%3}, [%4];"
                 : "=r"(r[0]), "=r"(r[1]), "=r"(r[2]), "=r"(r[3]) : "r"(addr));
}
// fp32-accumulator fp16 mma
__device__ __forceinline__ void mma_f16(float* c, const unsigned* a,
                                        unsigned b0, unsigned b1) {
    asm volatile(
        "mma.sync.aligned.m16n8k16.row.col.f32.f16.f16.f32 "
        "{%0,%1,%2,%3}, {%4,%5,%6,%7}, {%8,%9}, {%0,%1,%2,%3};"
        : "+f"(c[0]), "+f"(c[1]), "+f"(c[2]), "+f"(c[3])
        : "r"(a[0]), "r"(a[1]), "r"(a[2]), "r"(a[3]), "r"(b0), "r"(b1));
}
// fp16-accumulator fp16 mma: C/D = 2 packed regs (half the acc registers)
__device__ __forceinline__ void mma_f16h(unsigned* c, const unsigned* a,
                                         unsigned b0, unsigned b1) {
    asm volatile(
        "mma.sync.aligned.m16n8k16.row.col.f16.f16.f16.f16 "
        "{%0,%1}, {%2,%3,%4,%5}, {%6,%7}, {%0,%1};"
        : "+r"(c[0]), "+r"(c[1])
        : "r"(a[0]), "r"(a[1]), "r"(a[2]), "r"(a[3]), "r"(b0), "r"(b1));
}
// 2^x elementwise on packed half2 (in place on fragment regs)
__device__ __forceinline__ unsigned ex2p(unsigned x) {
    unsigned o;
    asm("ex2.approx.f16x2 %0, %1;" : "=r"(o) : "r"(x));
    return o;
}

// ---------------------------------------------------------------------------
// Kernel 1: q/k/v = LN(x^T @ W). Block = 64 consecutive f.
// q scaled by 0.125*log2(e) so downstream uses raw ex2.
// ---------------------------------------------------------------------------
__device__ __forceinline__ void ln64(float& a0, float& a1, float scale) {
    float s = a0 + a1;
    #pragma unroll
    for (int o = 16; o; o >>= 1) s += __shfl_xor_sync(0xffffffffu, s, o);
    float mu = s * (1.0f / 64.0f);
    float t0 = a0 - mu, t1 = a1 - mu;
    float ss = t0 * t0 + t1 * t1;
    #pragma unroll
    for (int o = 16; o; o >>= 1) ss += __shfl_xor_sync(0xffffffffu, ss, o);
    float r = rsqrtf(ss * (1.0f / 64.0f) + 1e-5f) * scale;
    a0 = t0 * r; a1 = t1 * r;
}

__global__ void __launch_bounds__(256) qkv_ln_kernel(
    const float* __restrict__ x,
    const float* __restrict__ Wq,
    const float* __restrict__ Wk,
    const float* __restrict__ Wv)
{
    __shared__ float sW2[3 * D_ * 64];  // interleaved: [(g*D+d)*32 + l]*2 + h
    __shared__ float sx[D_ * 64];
    int tid = threadIdx.x;
    int b  = blockIdx.x >> 6;
    int f0 = (blockIdx.x & 63) << 6;

    for (int idx = tid; idx < 3 * D_ * 64; idx += 256) {
        int g = idx / (D_ * 64), rem = idx % (D_ * 64);
        int d = rem >> 6, i = rem & 63;
        const float* W = (g == 0) ? Wq : (g == 1) ? Wk : Wv;
        sW2[(((g * D_ + d) * 32 + (i & 31)) << 1) + (i >> 5)] = W[d * I_ + i];
    }
    for (int i = tid; i < D_ * 64; i += 256) {
        int d = i >> 6, c = i & 63;
        sx[i] = x[(size_t)b * D_ * F_ + (size_t)d * F_ + f0 + c];
    }
    __syncthreads();

    int warp = tid >> 5, lane = tid & 31;
    int fbase = warp * 8;

    float acc[8][6] = {};
    #pragma unroll
    for (int dc = 0; dc < 40; dc += 4) {
        float wr[4][6];
        float xj[4][8];
        #pragma unroll
        for (int dd = 0; dd < 4; ++dd) {
            int d = dc + dd;
            if (d < D_) {
                float2 wq = *(float2*)&sW2[((0 * D_ + d) * 32 + lane) << 1];
                float2 wk = *(float2*)&sW2[((1 * D_ + d) * 32 + lane) << 1];
                float2 wv = *(float2*)&sW2[((2 * D_ + d) * 32 + lane) << 1];
                wr[dd][0] = wq.x; wr[dd][1] = wq.y;
                wr[dd][2] = wk.x; wr[dd][3] = wk.y;
                wr[dd][4] = wv.x; wr[dd][5] = wv.y;
                *(float4*)&xj[dd][0] = *(float4*)&sx[d * 64 + fbase];
                *(float4*)&xj[dd][4] = *(float4*)&sx[d * 64 + fbase + 4];
            } else {
                #pragma unroll
                for (int u = 0; u < 6; ++u) wr[dd][u] = 0.0f;
                #pragma unroll
                for (int u = 0; u < 8; ++u) xj[dd][u] = 0.0f;
            }
        }
        #pragma unroll
        for (int j = 0; j < 8; ++j) {
            #pragma unroll
            for (int dd = 0; dd < 4; ++dd) {
                float xd = xj[dd][j];
                acc[j][0] += xd * wr[dd][0];
                acc[j][1] += xd * wr[dd][1];
                acc[j][2] += xd * wr[dd][2];
                acc[j][3] += xd * wr[dd][3];
                acc[j][4] += xd * wr[dd][4];
                acc[j][5] += xd * wr[dd][5];
            }
        }
    }

    #pragma unroll
    for (int j = 0; j < 8; ++j) {
        ln64(acc[j][0], acc[j][1], 0.18033688f);   // 0.125 * log2(e)
        ln64(acc[j][2], acc[j][3], 1.0f);
        ln64(acc[j][4], acc[j][5], 1.0f);
        size_t ov = ((size_t)b * F_ + f0 + fbase + j) * I_ + lane;
        g_qh[ov] = __float2half_rn(acc[j][0]); g_qh[ov + 32] = __float2half_rn(acc[j][1]);
        g_kh[ov] = __float2half_rn(acc[j][2]); g_kh[ov + 32] = __float2half_rn(acc[j][3]);
        g_v [ov] = acc[j][4];                  g_v [ov + 32] = acc[j][5];
    }
}

// ---------------------------------------------------------------------------
// Kernel 2 (pass 1): c[n] = sum_m 2^(S[m][n]) AND g_vs = v/c, fused.
// fp16-accumulator mma halves acc registers; ex2.f16x2 applied directly to
// the accumulator fragments (no cvt). 3-stage q ring, ONE sync per chunk.
// ---------------------------------------------------------------------------
#define C1_SK   0u
#define C1_SQ   16384u
#define C1_QST  8192u
#define C1_SC   40960
#define C1_SMEM (40960 + 512)

__global__ void __launch_bounds__(128, 4) colsum_kernel() {
    extern __shared__ char sm[];
    unsigned sb = smem_u32(sm);
    float* scol = (float*)(sm + C1_SC);

    int tid = threadIdx.x, lane = tid & 31, w = tid >> 5;
    int n0 = blockIdx.x * 128, b = blockIdx.y;

    const __half* kv = g_kh + ((size_t)b * F_ + n0) * I_;
    const __half* qv = g_qh + (size_t)b * F_ * I_;

    int r = tid >> 3, c16 = tid & 7;
    #pragma unroll
    for (int j = 0; j < 8; ++j) {
        int row = r + j * 16;
        cp_async16(sb + C1_SK + SW128B((unsigned)(row * 128 + c16 * 16)),
                   kv + (size_t)row * I_ + c16 * 8);
    }
    #pragma unroll
    for (int j = 0; j < 4; ++j) {
        int row = r + j * 16;
        cp_async16(sb + C1_SQ + SW128B((unsigned)(row * 128 + c16 * 16)),
                   qv + (size_t)row * I_ + c16 * 8);
    }
    cp_commit();
    #pragma unroll
    for (int j = 0; j < 4; ++j) {
        int row = r + j * 16;
        cp_async16(sb + C1_SQ + C1_QST + SW128B((unsigned)(row * 128 + c16 * 16)),
                   qv + (size_t)(64 + row) * I_ + c16 * 8);
    }
    cp_commit();

    unsigned a_lrow = (unsigned)((lane & 7) + ((lane >> 3) & 1) * 8);
    unsigned a_koff = (unsigned)((lane >> 4) << 4);
    unsigned b_lrow = (unsigned)((lane & 7) + ((lane >> 4) << 3));
    unsigned b_koff = (unsigned)(((lane >> 3) & 1) << 4);

    float sumA[2] = {}, sumB[2] = {};   // rows r0 / r0+8 per mf

    int bs = 0;
    for (int t = 0; t < F_ / 64; ++t) {
        cp_wait<1>();
        __syncthreads();

        if (t + 2 < F_ / 64) {
            int nb = bs - 1; if (nb < 0) nb += 3;
            unsigned qd = sb + C1_SQ + (unsigned)nb * C1_QST;
            int kc = (t + 2) * 64;
            #pragma unroll
            for (int j = 0; j < 4; ++j) {
                int row = r + j * 16;
                cp_async16(qd + SW128B((unsigned)(row * 128 + c16 * 16)),
                           qv + (size_t)(kc + row) * I_ + c16 * 8);
            }
            cp_commit();
        }

        unsigned qbuf = sb + C1_SQ + (unsigned)bs * C1_QST;

        unsigned acc[2][8][2] = {};      // fp16 accumulators (packed)
        #pragma unroll
        for (int ks = 0; ks < 4; ++ks) {
            unsigned a[2][4], bB[4][4];
            #pragma unroll
            for (int mf = 0; mf < 2; ++mf) {
                unsigned row = (unsigned)(w * 32 + mf * 16) + a_lrow;
                ldm_x4(a[mf], sb + C1_SK + SW128B(row * 128 + a_koff + ks * 32));
            }
            #pragma unroll
            for (int np = 0; np < 4; ++np) {
                unsigned row = (unsigned)(np * 16) + b_lrow;
                ldm_x4(bB[np], qbuf + SW128B(row * 128 + b_koff + ks * 32));
            }
            #pragma unroll
            for (int mf = 0; mf < 2; ++mf)
                #pragma unroll
                for (int nf = 0; nf < 8; ++nf) {
                    int np = nf >> 1, s = nf & 1;
                    mma_f16h(acc[mf][nf], a[mf], bB[np][2 * s], bB[np][2 * s + 1]);
                }
        }

        #pragma unroll
        for (int mf = 0; mf < 2; ++mf)
            #pragma unroll
            for (int nf = 0; nf < 8; ++nf) {
                unsigned p01 = ex2p(acc[mf][nf][0]);   // row r0 (cols c, c+1)
                unsigned p23 = ex2p(acc[mf][nf][1]);   // row r0+8
                __half2 h01 = *(__half2*)&p01;
                __half2 h23 = *(__half2*)&p23;
                sumA[mf] += __low2float(h01) + __high2float(h01);
                sumB[mf] += __low2float(h23) + __high2float(h23);
            }

        if (++bs == 3) bs = 0;
    }

    #pragma unroll
    for (int o = 1; o <= 2; o <<= 1)
        #pragma unroll
        for (int mf = 0; mf < 2; ++mf) {
            sumA[mf] += __shfl_xor_sync(0xffffffffu, sumA[mf], o);
            sumB[mf] += __shfl_xor_sync(0xffffffffu, sumB[mf], o);
        }
    if ((lane & 3) == 0) {
        int nl = w * 32 + (lane >> 2);
        #pragma unroll
        for (int mf = 0; mf < 2; ++mf) {
            scol[nl + mf * 16]     = sumA[mf];
            scol[nl + mf * 16 + 8] = sumB[mf];
        }
    }
    __syncthreads();

    // ---- fused vscale: g_vs[row][i] = fp16(v[row][i] / c[row]) ----
    {
        int row = tid >> 1;
        int ih = (tid & 1) * 32;
        float rc = 1.0f / scol[row];
        const float* vp = g_v + ((size_t)b * F_ + n0 + row) * I_ + ih;
        __half* vo = g_vs + ((size_t)b * F_ + n0 + row) * I_ + ih;
        #pragma unroll
        for (int u = 0; u < 4; ++u) {
            float4 v0 = *(const float4*)(vp + u * 8);
            float4 v1 = *(const float4*)(vp + u * 8 + 4);
            __half2 h[4];
            h[0] = __floats2half2_rn(v0.x * rc, v0.y * rc);
            h[1] = __floats2half2_rn(v0.z * rc, v0.w * rc);
            h[2] = __floats2half2_rn(v1.x * rc, v1.y * rc);
            h[3] = __floats2half2_rn(v1.z * rc, v1.w * rc);
            *(uint4*)(vo + u * 8) = *(uint4*)h;
        }
        int row2 = row + 64;
        float rc2 = 1.0f / scol[row2];
        const float* vp2 = g_v + ((size_t)b * F_ + n0 + row2) * I_ + ih;
        __half* vo2 = g_vs + ((size_t)b * F_ + n0 + row2) * I_ + ih;
        #pragma unroll
        for (int u = 0; u < 4; ++u) {
            float4 v0 = *(const float4*)(vp2 + u * 8);
            float4 v1 = *(const float4*)(vp2 + u * 8 + 4);
            __half2 h[4];
            h[0] = __floats2half2_rn(v0.x * rc2, v0.y * rc2);
            h[1] = __floats2half2_rn(v0.z * rc2, v0.w * rc2);
            h[2] = __floats2half2_rn(v1.x * rc2, v1.y * rc2);
            h[3] = __floats2half2_rn(v1.z * rc2, v1.w * rc2);
            *(uint4*)(vo2 + u * 8) = *(uint4*)h;
        }
    }
}

// ---------------------------------------------------------------------------
// Kernel 3 (pass 2): fused QK -> 2^S -> AV. No P in global memory.
// fp16-accumulator S mma: D fragments ARE the AV A fragments after an
// in-place ex2.f16x2 (no cvt, no repack). Regs <= 128 -> 4 CTAs/SM with a
// 2-stage 48KB ring -> all 512 CTAs in ONE wave.
// ---------------------------------------------------------------------------
#define F2_SQ   0u
#define F2_ST   16384u      // 2 stages x (k 8KB + v 8KB)
#define F2_STSZ 16384u
#define F2_SMEM (16384 + 2 * 16384)

__global__ void __launch_bounds__(128, 4) fused_av_kernel(float* __restrict__ out) {
    extern __shared__ char sm[];
    unsigned sb = smem_u32(sm);

    int tid = threadIdx.x, lane = tid & 31, w = tid >> 5;
    int m0 = blockIdx.x * 128, b = blockIdx.y;

    const __half* qv = g_qh + ((size_t)b * F_ + m0) * I_;
    const __half* kv = g_kh + (size_t)b * F_ * I_;
    const __half* vv = g_vs + (size_t)b * F_ * I_;

    int r = tid >> 3, c16 = tid & 7;
    // group 0: q tile + k0 + v0
    #pragma unroll
    for (int j = 0; j < 8; ++j) {
        int row = r + j * 16;
        cp_async16(sb + F2_SQ + SW128B((unsigned)(row * 128 + c16 * 16)),
                   qv + (size_t)row * I_ + c16 * 8);
    }
    #pragma unroll
    for (int j = 0; j < 4; ++j) {
        int row = r + j * 16;
        cp_async16(sb + F2_ST + SW128B((unsigned)(row * 128 + c16 * 16)),
                   kv + (size_t)row * I_ + c16 * 8);
        cp_async16(sb + F2_ST + 8192u + SW128B((unsigned)(row * 128 + c16 * 16)),
                   vv + (size_t)row * I_ + c16 * 8);
    }
    cp_commit();
    // group 1: k1 + v1
    #pragma unroll
    for (int j = 0; j < 4; ++j) {
        int row = r + j * 16;
        cp_async16(sb + F2_ST + F2_STSZ + SW128B((unsigned)(row * 128 + c16 * 16)),
                   kv + (size_t)(64 + row) * I_ + c16 * 8);
        cp_async16(sb + F2_ST + F2_STSZ + 8192u + SW128B((unsigned)(row * 128 + c16 * 16)),
                   vv + (size_t)(64 + row) * I_ + c16 * 8);
    }
    cp_commit();

    unsigned a_lrow = (unsigned)((lane & 7) + ((lane >> 3) & 1) * 8);
    unsigned a_koff = (unsigned)((lane >> 4) << 4);
    unsigned b_lrow = (unsigned)((lane & 7) + ((lane >> 4) << 3));
    unsigned b_koff = (unsigned)(((lane >> 3) & 1) << 4);
    unsigned bt_base = (unsigned)((lane & 15) * 128 + ((lane >> 4) << 4));

    float acc_o[2][8][4] = {};     // persistent output accumulator

    for (int t = 0; t < F_ / 64; ++t) {
        if (t + 1 < F_ / 64) cp_wait<1>();
        else                 cp_wait<0>();
        __syncthreads();           // buffer t ready

        unsigned kbuf = sb + F2_ST + (unsigned)(t & 1) * F2_STSZ;
        unsigned vbuf = kbuf + 8192u;

        // ---- S mma (fp16 accumulators) ----
        unsigned acc_s[2][8][2] = {};
        #pragma unroll
        for (int ks = 0; ks < 4; ++ks) {
            unsigned a[2][4], bB[4][4];
            #pragma unroll
            for (int mf = 0; mf < 2; ++mf) {
                unsigned row = (unsigned)(w * 32 + mf * 16) + a_lrow;
                ldm_x4(a[mf], sb + F2_SQ + SW128B(row * 128 + a_koff + ks * 32));
            }
            #pragma unroll
            for (int np = 0; np < 4; ++np) {
                unsigned row = (unsigned)(np * 16) + b_lrow;
                ldm_x4(bB[np], kbuf + SW128B(row * 128 + b_koff + ks * 32));
            }
            #pragma unroll
            for (int mf = 0; mf < 2; ++mf)
                #pragma unroll
                for (int nf = 0; nf < 8; ++nf) {
                    int np = nf >> 1, s = nf & 1;
                    mma_f16h(acc_s[mf][nf], a[mf], bB[np][2 * s], bB[np][2 * s + 1]);
                }
        }

        // ---- per-k16-step: in-place ex2 on fragments + AV mma ----
        #pragma unroll
        for (int s = 0; s < 4; ++s) {
            unsigned pa[2][4];
            #pragma unroll
            for (int mf = 0; mf < 2; ++mf) {
                pa[mf][0] = ex2p(acc_s[mf][2 * s][0]);
                pa[mf][1] = ex2p(acc_s[mf][2 * s][1]);
                pa[mf][2] = ex2p(acc_s[mf][2 * s + 1][0]);
                pa[mf][3] = ex2p(acc_s[mf][2 * s + 1][1]);
            }
            unsigned bv[4][4];
            #pragma unroll
            for (int p = 0; p < 4; ++p)
                ldm_x4_t(bv[p], vbuf + SW128B(bt_base + s * 2048 + p * 32));
            #pragma unroll
            for (int mf = 0; mf < 2; ++mf)
                #pragma unroll
                for (int p = 0; p < 4; ++p) {
                    mma_f16(acc_o[mf][2 * p],     pa[mf], bv[p][0], bv[p][1]);
                    mma_f16(acc_o[mf][2 * p + 1], pa[mf], bv[p][2], bv[p][3]);
                }
        }

        __syncthreads();           // all warps done reading buffer t
        if (t + 2 < F_ / 64) {
            int kc = (t + 2) * 64;
            unsigned kd = sb + F2_ST + (unsigned)(t & 1) * F2_STSZ;
            unsigned vd = kd + 8192u;
            #pragma unroll
            for (int j = 0; j < 4; ++j) {
                int row = r + j * 16;
                cp_async16(kd + SW128B((unsigned)(row * 128 + c16 * 16)),
                           kv + (size_t)(kc + row) * I_ + c16 * 8);
                cp_async16(vd + SW128B((unsigned)(row * 128 + c16 * 16)),
                           vv + (size_t)(kc + row) * I_ + c16 * 8);
            }
            cp_commit();
        }
    }

    int r0 = lane >> 2, c2 = (lane & 3) * 2;
    #pragma unroll
    for (int mf = 0; mf < 2; ++mf) {
        int mrow = m0 + w * 32 + mf * 16 + r0;
        float* o0 = out + ((size_t)b * F_ + mrow) * I_ + c2;
        float* o1 = o0 + 8 * I_;
        #pragma unroll
        for (int it = 0; it < 8; ++it) {
            *(float2*)(o0 + it * 8) = make_float2(acc_o[mf][it][0], acc_o[mf][it][1]);
            *(float2*)(o1 + it * 8) = make_float2(acc_o[mf][it][2], acc_o[mf][it][3]);
        }
    }
}

// ---------------------------------------------------------------------------
extern "C" void kernel_launch(void* const* d_in, const int* in_sizes, int n_in,
                              void* d_out, int out_size)
{
    const float* x  = (const float*)d_in[0];
    const float* Wq = (const float*)d_in[1];
    const float* Wk = (const float*)d_in[2];
    const float* Wv = (const float*)d_in[3];
    float* out = (float*)d_out;

    static bool attr_done = false;
    if (!attr_done) {
        cudaFuncSetAttribute(colsum_kernel,
                             cudaFuncAttributeMaxDynamicSharedMemorySize, C1_SMEM);
        cudaFuncSetAttribute(fused_av_kernel,
                             cudaFuncAttributeMaxDynamicSharedMemorySize, F2_SMEM);
        attr_done = true;
    }

    qkv_ln_kernel<<<B_ * F_ / 64, 256>>>(x, Wq, Wk, Wv);
    colsum_kernel<<<dim3(F_ / 128, B_), 128, C1_SMEM>>>();
    fused_av_kernel<<<dim3(F_ / 128, B_), 128, F2_SMEM>>>(out);
}

// round 17
// speedup vs baseline: 1.0811x; 1.0625x over previous
#include <cuda_runtime.h>
#include <cuda_fp16.h>
#include <cstdint>
#include <math.h>

#define B_ 16
#define D_ 37
#define F_ 4096
#define I_ 64

// ---- scratch (static device globals: allocation-free) ----
__device__ __half g_qh[B_ * F_ * I_];                // [b][f][i], LN'd, *0.125*log2e, fp16
__device__ __half g_kh[B_ * F_ * I_];                // [b][f][i], LN'd, fp16
__device__ float  g_v [B_ * F_ * I_];                // [b][f][i], LN'd fp32
__device__ __half g_vs[B_ * F_ * I_];                // Vs[b][n][i] = v[n][i]/c[n], fp16

#define SW128B(o) ((o) ^ (((o) >> 3) & 0x70))

// ======================= PTX helpers (arch-generic, sm_80+) ==================
__device__ __forceinline__ unsigned smem_u32(const void* p) {
    unsigned a;
    asm("{ .reg .u64 t; cvta.to.shared.u64 t, %1; cvt.u32.u64 %0, t; }"
        : "=r"(a) : "l"(p));
    return a;
}
__device__ __forceinline__ void cp_async16(unsigned dst, const void* src) {
    asm volatile("cp.async.cg.shared.global [%0], [%1], 16;" :: "r"(dst), "l"(src));
}
__device__ __forceinline__ void cp_commit() {
    asm volatile("cp.async.commit_group;" ::: "memory");
}
template <int N>
__device__ __forceinline__ void cp_wait() {
    asm volatile("cp.async.wait_group %0;" :: "n"(N) : "memory");
}
__device__ __forceinline__ void ldm_x4(unsigned* r, unsigned addr) {
    asm volatile("ldmatrix.sync.aligned.m8n8.x4.shared.b16 {%0,%1,%2,%3}, [%4];"
                 : "=r"(r[0]), "=r"(r[1]), "=r"(r[2]), "=r"(r[3]) : "r"(addr));
}
__device__ __forceinline__ void ldm_x4_t(unsigned* r, unsigned addr) {
    asm volatile("ldmatrix.sync.aligned.m8n8.x4.trans.shared.b16 {%0,%1,%2,%3}, [%4];"
                 : "=r"(r[0]), "=r"(r[1]), "=r"(r[2]), "=r"(r[3]) : "r"(addr));
}
// fp32-accumulator fp16 mma
__device__ __forceinline__ void mma_f16(float* c, const unsigned* a,
                                        unsigned b0, unsigned b1) {
    asm volatile(
        "mma.sync.aligned.m16n8k16.row.col.f32.f16.f16.f32 "
        "{%0,%1,%2,%3}, {%4,%5,%6,%7}, {%8,%9}, {%0,%1,%2,%3};"
        : "+f"(c[0]), "+f"(c[1]), "+f"(c[2]), "+f"(c[3])
        : "r"(a[0]), "r"(a[1]), "r"(a[2]), "r"(a[3]), "r"(b0), "r"(b1));
}
// fp16-accumulator fp16 mma: C/D = 2 packed regs
__device__ __forceinline__ void mma_f16h(unsigned* c, const unsigned* a,
                                         unsigned b0, unsigned b1) {
    asm volatile(
        "mma.sync.aligned.m16n8k16.row.col.f16.f16.f16.f16 "
        "{%0,%1}, {%2,%3,%4,%5}, {%6,%7}, {%0,%1};"
        : "+r"(c[0]), "+r"(c[1])
        : "r"(a[0]), "r"(a[1]), "r"(a[2]), "r"(a[3]), "r"(b0), "r"(b1));
}
// 2^x elementwise on packed half2
__device__ __forceinline__ unsigned ex2p(unsigned x) {
    unsigned o;
    asm("ex2.approx.f16x2 %0, %1;" : "=r"(o) : "r"(x));
    return o;
}

// ---------------------------------------------------------------------------
// Kernel 1: q/k/v = LN(x^T @ W). Block = 64 consecutive f.
// q scaled by 0.125*log2(e) so downstream uses raw ex2.
// ---------------------------------------------------------------------------
__device__ __forceinline__ void ln64(float& a0, float& a1, float scale) {
    float s = a0 + a1;
    #pragma unroll
    for (int o = 16; o; o >>= 1) s += __shfl_xor_sync(0xffffffffu, s, o);
    float mu = s * (1.0f / 64.0f);
    float t0 = a0 - mu, t1 = a1 - mu;
    float ss = t0 * t0 + t1 * t1;
    #pragma unroll
    for (int o = 16; o; o >>= 1) ss += __shfl_xor_sync(0xffffffffu, ss, o);
    float r = rsqrtf(ss * (1.0f / 64.0f) + 1e-5f) * scale;
    a0 = t0 * r; a1 = t1 * r;
}

__global__ void __launch_bounds__(256) qkv_ln_kernel(
    const float* __restrict__ x,
    const float* __restrict__ Wq,
    const float* __restrict__ Wk,
    const float* __restrict__ Wv)
{
    __shared__ float sW2[3 * D_ * 64];
    __shared__ float sx[D_ * 64];
    int tid = threadIdx.x;
    int b  = blockIdx.x >> 6;
    int f0 = (blockIdx.x & 63) << 6;

    for (int idx = tid; idx < 3 * D_ * 64; idx += 256) {
        int g = idx / (D_ * 64), rem = idx % (D_ * 64);
        int d = rem >> 6, i = rem & 63;
        const float* W = (g == 0) ? Wq : (g == 1) ? Wk : Wv;
        sW2[(((g * D_ + d) * 32 + (i & 31)) << 1) + (i >> 5)] = W[d * I_ + i];
    }
    for (int i = tid; i < D_ * 64; i += 256) {
        int d = i >> 6, c = i & 63;
        sx[i] = x[(size_t)b * D_ * F_ + (size_t)d * F_ + f0 + c];
    }
    __syncthreads();

    int warp = tid >> 5, lane = tid & 31;
    int fbase = warp * 8;

    float acc[8][6] = {};
    #pragma unroll
    for (int dc = 0; dc < 40; dc += 4) {
        float wr[4][6];
        float xj[4][8];
        #pragma unroll
        for (int dd = 0; dd < 4; ++dd) {
            int d = dc + dd;
            if (d < D_) {
                float2 wq = *(float2*)&sW2[((0 * D_ + d) * 32 + lane) << 1];
                float2 wk = *(float2*)&sW2[((1 * D_ + d) * 32 + lane) << 1];
                float2 wv = *(float2*)&sW2[((2 * D_ + d) * 32 + lane) << 1];
                wr[dd][0] = wq.x; wr[dd][1] = wq.y;
                wr[dd][2] = wk.x; wr[dd][3] = wk.y;
                wr[dd][4] = wv.x; wr[dd][5] = wv.y;
                *(float4*)&xj[dd][0] = *(float4*)&sx[d * 64 + fbase];
                *(float4*)&xj[dd][4] = *(float4*)&sx[d * 64 + fbase + 4];
            } else {
                #pragma unroll
                for (int u = 0; u < 6; ++u) wr[dd][u] = 0.0f;
                #pragma unroll
                for (int u = 0; u < 8; ++u) xj[dd][u] = 0.0f;
            }
        }
        #pragma unroll
        for (int j = 0; j < 8; ++j) {
            #pragma unroll
            for (int dd = 0; dd < 4; ++dd) {
                float xd = xj[dd][j];
                acc[j][0] += xd * wr[dd][0];
                acc[j][1] += xd * wr[dd][1];
                acc[j][2] += xd * wr[dd][2];
                acc[j][3] += xd * wr[dd][3];
                acc[j][4] += xd * wr[dd][4];
                acc[j][5] += xd * wr[dd][5];
            }
        }
    }

    #pragma unroll
    for (int j = 0; j < 8; ++j) {
        ln64(acc[j][0], acc[j][1], 0.18033688f);   // 0.125 * log2(e)
        ln64(acc[j][2], acc[j][3], 1.0f);
        ln64(acc[j][4], acc[j][5], 1.0f);
        size_t ov = ((size_t)b * F_ + f0 + fbase + j) * I_ + lane;
        g_qh[ov] = __float2half_rn(acc[j][0]); g_qh[ov + 32] = __float2half_rn(acc[j][1]);
        g_kh[ov] = __float2half_rn(acc[j][2]); g_kh[ov + 32] = __float2half_rn(acc[j][3]);
        g_v [ov] = acc[j][4];                  g_v [ov + 32] = acc[j][5];
    }
}

// ---------------------------------------------------------------------------
// Kernel 2 (pass 1): c[n] = sum_m 2^(S[m][n]) AND g_vs = v/c, fused.
// fp16-accumulator mma; k A-fragments hoisted to registers (loop-invariant);
// 3-stage q ring, ONE sync per chunk, correct end-of-loop wait.
// ---------------------------------------------------------------------------
#define C1_SK   0u
#define C1_SQ   16384u
#define C1_QST  8192u
#define C1_SC   40960
#define C1_SMEM (40960 + 512)

__global__ void __launch_bounds__(128, 4) colsum_kernel() {
    extern __shared__ char sm[];
    unsigned sb = smem_u32(sm);
    float* scol = (float*)(sm + C1_SC);

    int tid = threadIdx.x, lane = tid & 31, w = tid >> 5;
    int n0 = blockIdx.x * 128, b = blockIdx.y;

    const __half* kv = g_kh + ((size_t)b * F_ + n0) * I_;
    const __half* qv = g_qh + (size_t)b * F_ * I_;

    int r = tid >> 3, c16 = tid & 7;
    #pragma unroll
    for (int j = 0; j < 8; ++j) {
        int row = r + j * 16;
        cp_async16(sb + C1_SK + SW128B((unsigned)(row * 128 + c16 * 16)),
                   kv + (size_t)row * I_ + c16 * 8);
    }
    #pragma unroll
    for (int j = 0; j < 4; ++j) {
        int row = r + j * 16;
        cp_async16(sb + C1_SQ + SW128B((unsigned)(row * 128 + c16 * 16)),
                   qv + (size_t)row * I_ + c16 * 8);
    }
    cp_commit();
    #pragma unroll
    for (int j = 0; j < 4; ++j) {
        int row = r + j * 16;
        cp_async16(sb + C1_SQ + C1_QST + SW128B((unsigned)(row * 128 + c16 * 16)),
                   qv + (size_t)(64 + row) * I_ + c16 * 8);
    }
    cp_commit();

    unsigned a_lrow = (unsigned)((lane & 7) + ((lane >> 3) & 1) * 8);
    unsigned a_koff = (unsigned)((lane >> 4) << 4);
    unsigned b_lrow = (unsigned)((lane & 7) + ((lane >> 4) << 3));
    unsigned b_koff = (unsigned)(((lane >> 3) & 1) << 4);

    // hoist loop-invariant k A-fragments (group 0 done after wait<1>)
    cp_wait<1>();
    __syncthreads();
    unsigned ka[2][4][4];
    #pragma unroll
    for (int ks = 0; ks < 4; ++ks)
        #pragma unroll
        for (int mf = 0; mf < 2; ++mf) {
            unsigned row = (unsigned)(w * 32 + mf * 16) + a_lrow;
            ldm_x4(ka[mf][ks], sb + C1_SK + SW128B(row * 128 + a_koff + ks * 32));
        }

    float sumA[2] = {}, sumB[2] = {};

    int bs = 0;
    for (int t = 0; t < F_ / 64; ++t) {
        if (t + 1 < F_ / 64) cp_wait<1>();
        else                 cp_wait<0>();
        __syncthreads();

        if (t + 2 < F_ / 64) {
            int nb = bs - 1; if (nb < 0) nb += 3;
            unsigned qd = sb + C1_SQ + (unsigned)nb * C1_QST;
            int kc = (t + 2) * 64;
            #pragma unroll
            for (int j = 0; j < 4; ++j) {
                int row = r + j * 16;
                cp_async16(qd + SW128B((unsigned)(row * 128 + c16 * 16)),
                           qv + (size_t)(kc + row) * I_ + c16 * 8);
            }
            cp_commit();
        }

        unsigned qbuf = sb + C1_SQ + (unsigned)bs * C1_QST;

        unsigned acc[2][8][2] = {};
        #pragma unroll
        for (int ks = 0; ks < 4; ++ks) {
            unsigned bB[4][4];
            #pragma unroll
            for (int np = 0; np < 4; ++np) {
                unsigned row = (unsigned)(np * 16) + b_lrow;
                ldm_x4(bB[np], qbuf + SW128B(row * 128 + b_koff + ks * 32));
            }
            #pragma unroll
            for (int mf = 0; mf < 2; ++mf)
                #pragma unroll
                for (int nf = 0; nf < 8; ++nf) {
                    int np = nf >> 1, s = nf & 1;
                    mma_f16h(acc[mf][nf], ka[mf][ks], bB[np][2 * s], bB[np][2 * s + 1]);
                }
        }

        #pragma unroll
        for (int mf = 0; mf < 2; ++mf)
            #pragma unroll
            for (int nf = 0; nf < 8; ++nf) {
                unsigned p01 = ex2p(acc[mf][nf][0]);
                unsigned p23 = ex2p(acc[mf][nf][1]);
                __half2 h01 = *(__half2*)&p01;
                __half2 h23 = *(__half2*)&p23;
                sumA[mf] += __low2float(h01) + __high2float(h01);
                sumB[mf] += __low2float(h23) + __high2float(h23);
            }

        if (++bs == 3) bs = 0;
    }

    #pragma unroll
    for (int o = 1; o <= 2; o <<= 1)
        #pragma unroll
        for (int mf = 0; mf < 2; ++mf) {
            sumA[mf] += __shfl_xor_sync(0xffffffffu, sumA[mf], o);
            sumB[mf] += __shfl_xor_sync(0xffffffffu, sumB[mf], o);
        }
    if ((lane & 3) == 0) {
        int nl = w * 32 + (lane >> 2);
        #pragma unroll
        for (int mf = 0; mf < 2; ++mf) {
            scol[nl + mf * 16]     = sumA[mf];
            scol[nl + mf * 16 + 8] = sumB[mf];
        }
    }
    __syncthreads();

    // ---- fused vscale: g_vs[row][i] = fp16(v[row][i] / c[row]) ----
    {
        int row = tid >> 1;
        int ih = (tid & 1) * 32;
        float rc = 1.0f / scol[row];
        const float* vp = g_v + ((size_t)b * F_ + n0 + row) * I_ + ih;
        __half* vo = g_vs + ((size_t)b * F_ + n0 + row) * I_ + ih;
        #pragma unroll
        for (int u = 0; u < 4; ++u) {
            float4 v0 = *(const float4*)(vp + u * 8);
            float4 v1 = *(const float4*)(vp + u * 8 + 4);
            __half2 h[4];
            h[0] = __floats2half2_rn(v0.x * rc, v0.y * rc);
            h[1] = __floats2half2_rn(v0.z * rc, v0.w * rc);
            h[2] = __floats2half2_rn(v1.x * rc, v1.y * rc);
            h[3] = __floats2half2_rn(v1.z * rc, v1.w * rc);
            *(uint4*)(vo + u * 8) = *(uint4*)h;
        }
        int row2 = row + 64;
        float rc2 = 1.0f / scol[row2];
        const float* vp2 = g_v + ((size_t)b * F_ + n0 + row2) * I_ + ih;
        __half* vo2 = g_vs + ((size_t)b * F_ + n0 + row2) * I_ + ih;
        #pragma unroll
        for (int u = 0; u < 4; ++u) {
            float4 v0 = *(const float4*)(vp2 + u * 8);
            float4 v1 = *(const float4*)(vp2 + u * 8 + 4);
            __half2 h[4];
            h[0] = __floats2half2_rn(v0.x * rc2, v0.y * rc2);
            h[1] = __floats2half2_rn(v0.z * rc2, v0.w * rc2);
            h[2] = __floats2half2_rn(v1.x * rc2, v1.y * rc2);
            h[3] = __floats2half2_rn(v1.z * rc2, v1.w * rc2);
            *(uint4*)(vo2 + u * 8) = *(uint4*)h;
        }
    }
}

// ---------------------------------------------------------------------------
// Kernel 3 (pass 2): fused QK -> 2^S -> AV. No P in global memory.
// q A-fragments hoisted (loop-invariant). fp16 S accumulators; in-place
// ex2.f16x2 makes them the AV A fragments. 3-stage k/v ring, ONE sync/chunk.
// ---------------------------------------------------------------------------
#define F2_SQ   0u
#define F2_ST   16384u      // 3 stages x (k 8KB + v 8KB)
#define F2_STSZ 16384u
#define F2_SMEM (16384 + 3 * 16384)

__global__ void __launch_bounds__(128, 3) fused_av_kernel(float* __restrict__ out) {
    extern __shared__ char sm[];
    unsigned sb = smem_u32(sm);

    int tid = threadIdx.x, lane = tid & 31, w = tid >> 5;
    int m0 = blockIdx.x * 128, b = blockIdx.y;

    const __half* qv = g_qh + ((size_t)b * F_ + m0) * I_;
    const __half* kv = g_kh + (size_t)b * F_ * I_;
    const __half* vv = g_vs + (size_t)b * F_ * I_;

    int r = tid >> 3, c16 = tid & 7;
    // group 0: q tile + k0 + v0
    #pragma unroll
    for (int j = 0; j < 8; ++j) {
        int row = r + j * 16;
        cp_async16(sb + F2_SQ + SW128B((unsigned)(row * 128 + c16 * 16)),
                   qv + (size_t)row * I_ + c16 * 8);
    }
    #pragma unroll
    for (int j = 0; j < 4; ++j) {
        int row = r + j * 16;
        cp_async16(sb + F2_ST + SW128B((unsigned)(row * 128 + c16 * 16)),
                   kv + (size_t)row * I_ + c16 * 8);
        cp_async16(sb + F2_ST + 8192u + SW128B((unsigned)(row * 128 + c16 * 16)),
                   vv + (size_t)row * I_ + c16 * 8);
    }
    cp_commit();
    // group 1: k1 + v1
    #pragma unroll
    for (int j = 0; j < 4; ++j) {
        int row = r + j * 16;
        cp_async16(sb + F2_ST + F2_STSZ + SW128B((unsigned)(row * 128 + c16 * 16)),
                   kv + (size_t)(64 + row) * I_ + c16 * 8);
        cp_async16(sb + F2_ST + F2_STSZ + 8192u + SW128B((unsigned)(row * 128 + c16 * 16)),
                   vv + (size_t)(64 + row) * I_ + c16 * 8);
    }
    cp_commit();

    unsigned a_lrow = (unsigned)((lane & 7) + ((lane >> 3) & 1) * 8);
    unsigned a_koff = (unsigned)((lane >> 4) << 4);
    unsigned b_lrow = (unsigned)((lane & 7) + ((lane >> 4) << 3));
    unsigned b_koff = (unsigned)(((lane >> 3) & 1) << 4);
    unsigned bt_base = (unsigned)((lane & 15) * 128 + ((lane >> 4) << 4));

    // hoist loop-invariant q A-fragments (group 0 done after wait<1>)
    cp_wait<1>();
    __syncthreads();
    unsigned qa[2][4][4];
    #pragma unroll
    for (int ks = 0; ks < 4; ++ks)
        #pragma unroll
        for (int mf = 0; mf < 2; ++mf) {
            unsigned row = (unsigned)(w * 32 + mf * 16) + a_lrow;
            ldm_x4(qa[mf][ks], sb + F2_SQ + SW128B(row * 128 + a_koff + ks * 32));
        }

    float acc_o[2][8][4] = {};

    int bs = 0;
    for (int t = 0; t < F_ / 64; ++t) {
        if (t + 1 < F_ / 64) cp_wait<1>();
        else                 cp_wait<0>();
        __syncthreads();

        if (t + 2 < F_ / 64) {
            int nb = bs - 1; if (nb < 0) nb += 3;
            unsigned kd = sb + F2_ST + (unsigned)nb * F2_STSZ;
            int kc = (t + 2) * 64;
            #pragma unroll
            for (int j = 0; j < 4; ++j) {
                int row = r + j * 16;
                cp_async16(kd + SW128B((unsigned)(row * 128 + c16 * 16)),
                           kv + (size_t)(kc + row) * I_ + c16 * 8);
                cp_async16(kd + 8192u + SW128B((unsigned)(row * 128 + c16 * 16)),
                           vv + (size_t)(kc + row) * I_ + c16 * 8);
            }
            cp_commit();
        }

        unsigned kbuf = sb + F2_ST + (unsigned)bs * F2_STSZ;
        unsigned vbuf = kbuf + 8192u;

        // ---- S mma (fp16 accumulators) ----
        unsigned acc_s[2][8][2] = {};
        #pragma unroll
        for (int ks = 0; ks < 4; ++ks) {
            unsigned bB[4][4];
            #pragma unroll
            for (int np = 0; np < 4; ++np) {
                unsigned row = (unsigned)(np * 16) + b_lrow;
                ldm_x4(bB[np], kbuf + SW128B(row * 128 + b_koff + ks * 32));
            }
            #pragma unroll
            for (int mf = 0; mf < 2; ++mf)
                #pragma unroll
                for (int nf = 0; nf < 8; ++nf) {
                    int np = nf >> 1, s = nf & 1;
                    mma_f16h(acc_s[mf][nf], qa[mf][ks], bB[np][2 * s], bB[np][2 * s + 1]);
                }
        }

        // ---- per-k16-step: in-place ex2 on fragments + AV mma ----
        #pragma unroll
        for (int s = 0; s < 4; ++s) {
            unsigned pa[2][4];
            #pragma unroll
            for (int mf = 0; mf < 2; ++mf) {
                pa[mf][0] = ex2p(acc_s[mf][2 * s][0]);
                pa[mf][1] = ex2p(acc_s[mf][2 * s][1]);
                pa[mf][2] = ex2p(acc_s[mf][2 * s + 1][0]);
                pa[mf][3] = ex2p(acc_s[mf][2 * s + 1][1]);
            }
            unsigned bv[4][4];
            #pragma unroll
            for (int p = 0; p < 4; ++p)
                ldm_x4_t(bv[p], vbuf + SW128B(bt_base + s * 2048 + p * 32));
            #pragma unroll
            for (int mf = 0; mf < 2; ++mf)
                #pragma unroll
                for (int p = 0; p < 4; ++p) {
                    mma_f16(acc_o[mf][2 * p],     pa[mf], bv[p][0], bv[p][1]);
                    mma_f16(acc_o[mf][2 * p + 1], pa[mf], bv[p][2], bv[p][3]);
                }
        }

        if (++bs == 3) bs = 0;
    }

    int r0 = lane >> 2, c2 = (lane & 3) * 2;
    #pragma unroll
    for (int mf = 0; mf < 2; ++mf) {
        int mrow = m0 + w * 32 + mf * 16 + r0;
        float* o0 = out + ((size_t)b * F_ + mrow) * I_ + c2;
        float* o1 = o0 + 8 * I_;
        #pragma unroll
        for (int it = 0; it < 8; ++it) {
            *(float2*)(o0 + it * 8) = make_float2(acc_o[mf][it][0], acc_o[mf][it][1]);
            *(float2*)(o1 + it * 8) = make_float2(acc_o[mf][it][2], acc_o[mf][it][3]);
        }
    }
}

// ---------------------------------------------------------------------------
extern "C" void kernel_launch(void* const* d_in, const int* in_sizes, int n_in,
                              void* d_out, int out_size)
{
    const float* x  = (const float*)d_in[0];
    const float* Wq = (const float*)d_in[1];
    const float* Wk = (const float*)d_in[2];
    const float* Wv = (const float*)d_in[3];
    float* out = (float*)d_out;

    static bool attr_done = false;
    if (!attr_done) {
        cudaFuncSetAttribute(colsum_kernel,
                             cudaFuncAttributeMaxDynamicSharedMemorySize, C1_SMEM);
        cudaFuncSetAttribute(fused_av_kernel,
                             cudaFuncAttributeMaxDynamicSharedMemorySize, F2_SMEM);
        attr_done = true;
    }

    qkv_ln_kernel<<<B_ * F_ / 64, 256>>>(x, Wq, Wk, Wv);
    colsum_kernel<<<dim3(F_ / 128, B_), 128, C1_SMEM>>>();
    fused_av_kernel<<<dim3(F_ / 128, B_), 128, F2_SMEM>>>(out);
}